// round 12
// baseline (speedup 1.0000x reference)
#include <cuda_runtime.h>
#include <cuda_bf16.h>

// ---------------------------------------------------------------------------
// DiffAttention — R9: q-tile 128 (each warp m32 = 2 x m16 A-tiles) to amortize
// K/V ldmatrix over 2x MMA work (L1 was 62.6% = co-bottleneck). Halves
// (attn1/attn2) processed sequentially to cap register liveness.
// ---------------------------------------------------------------------------

#define NTOK   4096
#define HEADS  4
#define NCHUNK 4
#define MPER   (NTOK / NCHUNK)     // 1024 keys per chunk
#define NIT    (MPER / 64)         // 16 key-tiles
#define STAGE  14848               // KH 5120 + KL 5120 + V 4608
#define LAMBDA 0.1f

// Scratch (static device globals; no allocation allowed)
__device__ float g_xs [128 * NTOK];
__device__ float g_qkv[384 * NTOK];
__device__ __nv_bfloat16 g_qh[HEADS * NTOK * 32];   // [h][n][d] (scale*log2e folded)
__device__ __nv_bfloat16 g_ql[HEADS * NTOK * 32];
__device__ __nv_bfloat16 g_kh[HEADS * NTOK * 32];
__device__ __nv_bfloat16 g_kl[HEADS * NTOK * 32];
__device__ __nv_bfloat16 g_vb[HEADS * 32 * NTOK];   // [h][d][n]
__device__ float g_po[NCHUNK * HEADS * NTOK * 64];  // [ch][h][n][2][32]
__device__ float g_pl[NCHUNK * HEADS * NTOK * 2];   // [ch][h][n][2]

// ---- PTX helpers ----------------------------------------------------------
__device__ __forceinline__ float ex2(float a) {
    float r; asm("ex2.approx.ftz.f32 %0, %1;" : "=f"(r) : "f"(a)); return r;
}
__device__ __forceinline__ unsigned cvt2(float hi, float lo) {
    unsigned d; asm("cvt.rn.bf16x2.f32 %0,%1,%2;" : "=r"(d) : "f"(hi), "f"(lo)); return d;
}
__device__ __forceinline__ void ldsm4(unsigned* r, unsigned a) {
    asm volatile("ldmatrix.sync.aligned.m8n8.x4.shared.b16 {%0,%1,%2,%3},[%4];"
                 : "=r"(r[0]), "=r"(r[1]), "=r"(r[2]), "=r"(r[3]) : "r"(a));
}
__device__ __forceinline__ void mma16816(float* c, const unsigned* a,
                                         unsigned b0, unsigned b1) {
    asm("mma.sync.aligned.m16n8k16.row.col.f32.bf16.bf16.f32 "
        "{%0,%1,%2,%3},{%4,%5,%6,%7},{%8,%9},{%0,%1,%2,%3};"
        : "+f"(c[0]), "+f"(c[1]), "+f"(c[2]), "+f"(c[3])
        : "r"(a[0]), "r"(a[1]), "r"(a[2]), "r"(a[3]), "r"(b0), "r"(b1));
}
__device__ __forceinline__ void cpa16(unsigned dst, const void* src) {
    asm volatile("cp.async.ca.shared.global [%0], [%1], 16;" :: "r"(dst), "l"(src));
}
__device__ __forceinline__ void cpa_commit() {
    asm volatile("cp.async.commit_group;");
}
template <int N> __device__ __forceinline__ void cpa_wait() {
    asm volatile("cp.async.wait_group %0;" :: "n"(N));
}

// ---------------------------------------------------------------------------
// Kernel 0: compact ::2 subsample -> g_xs[c][n]
// ---------------------------------------------------------------------------
__global__ __launch_bounds__(256) void gather_xs(const float* __restrict__ x)
{
    const int idx = blockIdx.x * 256 + threadIdx.x;
    const int n = idx & 4095, c = idx >> 12;
    const int hh = n >> 8, ww = (n >> 4) & 15, zz = n & 15;
    g_xs[idx] = x[c * 32768 + hh * 2048 + ww * 64 + zz * 2];
}

// ---------------------------------------------------------------------------
// Kernel 1: QKV projection GEMM with fused V->bf16 epilogue
// ---------------------------------------------------------------------------
__global__ __launch_bounds__(256) void qkv_proj(const float* __restrict__ w)
{
    __shared__ __align__(16) float ws[16][64];
    __shared__ __align__(16) float xs[16][128];

    const int tid = threadIdx.x;
    const int tx = tid & 15, ty = tid >> 4;
    const int n0 = blockIdx.x * 128, o0 = blockIdx.y * 64;

    float acc[4][8];
#pragma unroll
    for (int i = 0; i < 4; i++)
#pragma unroll
        for (int j = 0; j < 8; j++) acc[i][j] = 0.f;

    for (int c0 = 0; c0 < 128; c0 += 16) {
        __syncthreads();
        {
            const int o = tid >> 2, cc = (tid & 3) * 4;
            float4 wv = *(const float4*)&w[(o0 + o) * 128 + c0 + cc];
            ws[cc + 0][o] = wv.x; ws[cc + 1][o] = wv.y;
            ws[cc + 2][o] = wv.z; ws[cc + 3][o] = wv.w;
        }
#pragma unroll
        for (int r = 0; r < 2; r++) {
            const int i = tid * 2 + r, cc = i >> 5, f = i & 31;
            ((float4*)&xs[cc][0])[f] = *(const float4*)&g_xs[(c0 + cc) * NTOK + n0 + f * 4];
        }
        __syncthreads();
#pragma unroll
        for (int cc = 0; cc < 16; cc++) {
            const float4 wv = *(const float4*)&ws[cc][ty * 4];
            const float4 xa = *(const float4*)&xs[cc][tx * 8];
            const float4 xb = *(const float4*)&xs[cc][tx * 8 + 4];
            const float wr[4] = {wv.x, wv.y, wv.z, wv.w};
#pragma unroll
            for (int i = 0; i < 4; i++) {
                acc[i][0] += wr[i] * xa.x; acc[i][1] += wr[i] * xa.y;
                acc[i][2] += wr[i] * xa.z; acc[i][3] += wr[i] * xa.w;
                acc[i][4] += wr[i] * xb.x; acc[i][5] += wr[i] * xb.y;
                acc[i][6] += wr[i] * xb.z; acc[i][7] += wr[i] * xb.w;
            }
        }
    }
#pragma unroll
    for (int i = 0; i < 4; i++) {
        const int o = o0 + ty * 4 + i;
        float* dst = &g_qkv[o * NTOK + n0 + tx * 8];
        *(float4*)(dst)     = make_float4(acc[i][0], acc[i][1], acc[i][2], acc[i][3]);
        *(float4*)(dst + 4) = make_float4(acc[i][4], acc[i][5], acc[i][6], acc[i][7]);
        const int om = o % 96;
        if (om >= 64) {
            const int hd = (o / 96) * 32 + om - 64;
            uint4 vo;
            vo.x = cvt2(acc[i][1], acc[i][0]); vo.y = cvt2(acc[i][3], acc[i][2]);
            vo.z = cvt2(acc[i][5], acc[i][4]); vo.w = cvt2(acc[i][7], acc[i][6]);
            *(uint4*)(g_vb + (size_t)hd * NTOK + n0 + tx * 8) = vo;
        }
    }
}

// ---------------------------------------------------------------------------
// Kernel 2: Q/K -> bf16 hi/lo [h][n][d] via smem transpose
// ---------------------------------------------------------------------------
__global__ __launch_bounds__(128) void conv_qk()
{
    __shared__ float s[128][33];
    const int tid = threadIdx.x;
    const int h = blockIdx.y;
    const int n0 = blockIdx.x * 128;
    const int n = n0 + tid;
    const float SCLL = 0.17677669529663687f * 1.4426950408889634f;

#pragma unroll
    for (int pass = 0; pass < 2; pass++) {
        const float* src = g_qkv + (h * 96 + pass * 32) * NTOK;
        const float scl = pass ? 1.f : SCLL;
        __nv_bfloat16* dh = (pass ? g_kh : g_qh) + ((size_t)h * NTOK + n) * 32;
        __nv_bfloat16* dl = (pass ? g_kl : g_ql) + ((size_t)h * NTOK + n) * 32;

        __syncthreads();
#pragma unroll
        for (int d = 0; d < 32; d++) s[tid][d] = src[d * NTOK + n0 + tid];
        __syncthreads();

#pragma unroll
        for (int d0 = 0; d0 < 32; d0 += 8) {
            __nv_bfloat16 a[8], b[8];
#pragma unroll
            for (int dd = 0; dd < 8; dd++) {
                float v = s[tid][d0 + dd] * scl;
                __nv_bfloat16 x1 = __float2bfloat16(v);
                a[dd] = x1;
                b[dd] = __float2bfloat16(v - __bfloat162float(x1));
            }
            *(uint4*)(dh + d0) = *(uint4*)a;
            *(uint4*)(dl + d0) = *(uint4*)b;
        }
    }
}

// ---------------------------------------------------------------------------
// Kernel 3: warp-MMA flash attention; q-tile 128 (2 m16 A-tiles per warp).
// grid (32 q-tiles, 4 heads, 4 chunks) = 512 blocks, block 128.
// ---------------------------------------------------------------------------
__global__ __launch_bounds__(128) void attn_mma()
{
    __shared__ __align__(16) unsigned char sm[2 * STAGE];
    const int tid = threadIdx.x;
    const int lane = tid & 31, wp = tid >> 5;
    const int h = blockIdx.y;
    const int q0 = blockIdx.x * 128;
    const int ch = blockIdx.z;

    const unsigned sbase = (unsigned)__cvta_generic_to_shared(sm);

    // ---- stage Q (128 rows x 64B, rows padded to 80B), build A-frags
    {
        const char* qhp = (const char*)(g_qh + ((size_t)h * NTOK + q0) * 32);
        const char* qlp = (const char*)(g_ql + ((size_t)h * NTOK + q0) * 32);
#pragma unroll
        for (int r = 0; r < 4; r++) {
            int i = tid * 4 + r, row = i >> 2, c = i & 3;
            *(uint4*)(sm + row * 80 + c * 16)         = *(const uint4*)(qhp + row * 64 + c * 16);
            *(uint4*)(sm + 10240 + row * 80 + c * 16) = *(const uint4*)(qlp + row * 64 + c * 16);
        }
    }
    __syncthreads();
    unsigned Qh1[2][4], Qh2[2][4], Ql1[2][4], Ql2[2][4];
#pragma unroll
    for (int t = 0; t < 2; t++) {
        const unsigned ar = sbase + (wp * 32 + t * 16 + (lane & 15)) * 80 + (lane >> 4) * 16;
        ldsm4(Qh1[t], ar);
        ldsm4(Qh2[t], ar + 32);
        ldsm4(Ql1[t], ar + 10240);
        ldsm4(Ql2[t], ar + 10240 + 32);
    }
    __syncthreads();   // Q consumed; smem free for pipeline

    float O1[2][4][4], O2[2][4][4];
#pragma unroll
    for (int t = 0; t < 2; t++)
#pragma unroll
        for (int i = 0; i < 4; i++)
#pragma unroll
            for (int j = 0; j < 4; j++) { O1[t][i][j] = 0.f; O2[t][i][j] = 0.f; }
    float l1a[2] = {0.f, 0.f}, l1b[2] = {0.f, 0.f};
    float l2a[2] = {0.f, 0.f}, l2b[2] = {0.f, 0.f};

    const char* khp = (const char*)(g_kh + ((size_t)h * NTOK + ch * MPER) * 32);
    const char* klp = (const char*)(g_kl + ((size_t)h * NTOK + ch * MPER) * 32);
    const char* vbp = (const char*)(g_vb + (size_t)h * 32 * NTOK + ch * MPER);

    // cp.async geometry: per thread 2 KH + 2 KL + 2 V chunks (16B each)
    const int i0 = tid * 2, i1 = tid * 2 + 1;
    const int kr0 = i0 >> 2, kc0 = i0 & 3;
    const int kr1 = i1 >> 2, kc1 = i1 & 3;
    const int vr0 = i0 >> 3, vc0 = i0 & 7;
    const int vr1 = i1 >> 3, vc1 = i1 & 7;

    const char* skh0 = khp + kr0 * 64 + kc0 * 16;
    const char* skh1 = khp + kr1 * 64 + kc1 * 16;
    const char* skl0 = klp + kr0 * 64 + kc0 * 16;
    const char* skl1 = klp + kr1 * 64 + kc1 * 16;
    const char* svv0 = vbp + vr0 * 8192 + vc0 * 16;
    const char* svv1 = vbp + vr1 * 8192 + vc1 * 16;

    const unsigned dkh0 = kr0 * 80 + kc0 * 16;
    const unsigned dkh1 = kr1 * 80 + kc1 * 16;
    const unsigned dvv0 = 10240 + vr0 * 144 + vc0 * 16;
    const unsigned dvv1 = 10240 + vr1 * 144 + vc1 * 16;

    // B-fragment ldmatrix geometry
    const int bg = lane >> 3;
    const unsigned brow80  = (unsigned)(((bg >> 1) * 8 + (lane & 7)) * 80);
    const unsigned vrow144 = (unsigned)(((bg >> 1) * 8 + (lane & 7)) * 144);
    const unsigned bk16    = (unsigned)((bg & 1) * 16);

#define PREFETCH(stage, tile)                                            \
    do {                                                                 \
        const unsigned db = sbase + (stage) * STAGE;                     \
        const int ko = (tile) * (64 * 64);                               \
        const int vo = (tile) * 128;                                     \
        cpa16(db + dkh0,        skh0 + ko);                              \
        cpa16(db + dkh1,        skh1 + ko);                              \
        cpa16(db + 5120 + dkh0, skl0 + ko);                              \
        cpa16(db + 5120 + dkh1, skl1 + ko);                              \
        cpa16(db + dvv0,        svv0 + vo);                              \
        cpa16(db + dvv1,        svv1 + vo);                              \
        cpa_commit();                                                    \
    } while (0)

    PREFETCH(0, 0);

#pragma unroll 1
    for (int it = 0; it < NIT; it++) {
        if (it + 1 < NIT) {
            PREFETCH((it + 1) & 1, it + 1);
            cpa_wait<1>();
        } else {
            cpa_wait<0>();
        }
        __syncthreads();

        const unsigned sb = sbase + (it & 1) * STAGE;
        const unsigned sKH = sb, sKL = sb + 5120, sVV = sb + 10240;

#pragma unroll
        for (int np = 0; np < 4; np++) {
            const unsigned kra = (unsigned)(np * (16 * 80)) + brow80;
            const unsigned vca = (unsigned)(np * 32) + bk16;

            unsigned va[4], vb2[4];
            ldsm4(va,  sVV + vrow144 + vca);
            ldsm4(vb2, sVV + 16 * 144 + vrow144 + vca);

            // ---- half 1 (attn1: d0-15, hi/lo corrected) -> O1
            {
                unsigned kb[4], lb[4];
                ldsm4(kb, sKH + kra + bk16);
                ldsm4(lb, sKL + kra + bk16);
#pragma unroll
                for (int t = 0; t < 2; t++) {
                    float s[8] = {0, 0, 0, 0, 0, 0, 0, 0};
                    mma16816(s,     Qh1[t], kb[0], kb[1]);
                    mma16816(s,     Ql1[t], kb[0], kb[1]);
                    mma16816(s,     Qh1[t], lb[0], lb[1]);
                    mma16816(s + 4, Qh1[t], kb[2], kb[3]);
                    mma16816(s + 4, Ql1[t], kb[2], kb[3]);
                    mma16816(s + 4, Qh1[t], lb[2], lb[3]);

                    float p[8];
#pragma unroll
                    for (int e = 0; e < 8; e++) p[e] = ex2(s[e]);
                    l1a[t] += p[0] + p[1] + p[4] + p[5];
                    l1b[t] += p[2] + p[3] + p[6] + p[7];

                    unsigned P[4] = { cvt2(p[1], p[0]), cvt2(p[3], p[2]),
                                      cvt2(p[5], p[4]), cvt2(p[7], p[6]) };
                    mma16816(O1[t][0], P, va[0],  va[1]);
                    mma16816(O1[t][1], P, va[2],  va[3]);
                    mma16816(O1[t][2], P, vb2[0], vb2[1]);
                    mma16816(O1[t][3], P, vb2[2], vb2[3]);
                }
            }

            // ---- half 2 (attn2: d16-31) -> O2
            {
                unsigned kb[4], lb[4];
                ldsm4(kb, sKH + kra + 32 + bk16);
                ldsm4(lb, sKL + kra + 32 + bk16);
#pragma unroll
                for (int t = 0; t < 2; t++) {
                    float s[8] = {0, 0, 0, 0, 0, 0, 0, 0};
                    mma16816(s,     Qh2[t], kb[0], kb[1]);
                    mma16816(s,     Ql2[t], kb[0], kb[1]);
                    mma16816(s,     Qh2[t], lb[0], lb[1]);
                    mma16816(s + 4, Qh2[t], kb[2], kb[3]);
                    mma16816(s + 4, Ql2[t], kb[2], kb[3]);
                    mma16816(s + 4, Qh2[t], lb[2], lb[3]);

                    float p[8];
#pragma unroll
                    for (int e = 0; e < 8; e++) p[e] = ex2(s[e]);
                    l2a[t] += p[0] + p[1] + p[4] + p[5];
                    l2b[t] += p[2] + p[3] + p[6] + p[7];

                    unsigned P[4] = { cvt2(p[1], p[0]), cvt2(p[3], p[2]),
                                      cvt2(p[5], p[4]), cvt2(p[7], p[6]) };
                    mma16816(O2[t][0], P, va[0],  va[1]);
                    mma16816(O2[t][1], P, va[2],  va[3]);
                    mma16816(O2[t][2], P, vb2[0], vb2[1]);
                    mma16816(O2[t][3], P, vb2[2], vb2[3]);
                }
            }
        }
        __syncthreads();   // all warps done with this stage before overwrite
    }

    // ---- epilogue: reduce l across lanes, write partials
#pragma unroll
    for (int t = 0; t < 2; t++) {
        l1a[t] += __shfl_xor_sync(0xffffffffu, l1a[t], 1);
        l1a[t] += __shfl_xor_sync(0xffffffffu, l1a[t], 2);
        l1b[t] += __shfl_xor_sync(0xffffffffu, l1b[t], 1);
        l1b[t] += __shfl_xor_sync(0xffffffffu, l1b[t], 2);
        l2a[t] += __shfl_xor_sync(0xffffffffu, l2a[t], 1);
        l2a[t] += __shfl_xor_sync(0xffffffffu, l2a[t], 2);
        l2b[t] += __shfl_xor_sync(0xffffffffu, l2b[t], 1);
        l2b[t] += __shfl_xor_sync(0xffffffffu, l2b[t], 2);

        const int row = q0 + wp * 32 + t * 16 + (lane >> 2);
        const int colb = (lane & 3) * 2;
        float* po  = g_po + ((size_t)((ch * HEADS + h) * NTOK) + row) * 64;
        float* po8 = po + 8 * 64;
#pragma unroll
        for (int u = 0; u < 4; u++) {
            const int col = u * 8 + colb;
            *(float2*)(po  + col)      = make_float2(O1[t][u][0], O1[t][u][1]);
            *(float2*)(po  + 32 + col) = make_float2(O2[t][u][0], O2[t][u][1]);
            *(float2*)(po8 + col)      = make_float2(O1[t][u][2], O1[t][u][3]);
            *(float2*)(po8 + 32 + col) = make_float2(O2[t][u][2], O2[t][u][3]);
        }
        if ((lane & 3) == 0) {
            float* pl = g_pl + ((size_t)((ch * HEADS + h) * NTOK) + row) * 2;
            pl[0] = l1a[t]; pl[1] = l2a[t];
            pl[16] = l1b[t]; pl[17] = l2b[t];     // row+8
        }
    }
}

// ---------------------------------------------------------------------------
// Kernel 4: combine chunk partials -> out[h*131072 + n*32 + d]
// ---------------------------------------------------------------------------
__global__ __launch_bounds__(256) void reduce_out(float* __restrict__ out)
{
    const int idx = blockIdx.x * 256 + threadIdx.x;
    const int d  = idx & 31;
    const int hn = idx >> 5;

    float s1 = 0.f, s2 = 0.f, L1 = 0.f, L2 = 0.f;
#pragma unroll
    for (int ch = 0; ch < NCHUNK; ch++) {
        const float* po = g_po + (size_t)(ch * HEADS * NTOK + hn) * 64;
        s1 += po[d];
        s2 += po[32 + d];
        const float* pl = g_pl + (size_t)(ch * HEADS * NTOK + hn) * 2;
        L1 += pl[0];
        L2 += pl[1];
    }
    out[idx] = s1 / L1 - LAMBDA * s2 / L2;
}

// ---------------------------------------------------------------------------
extern "C" void kernel_launch(void* const* d_in, const int* in_sizes, int n_in,
                              void* d_out, int out_size)
{
    const float* x = (const float*)d_in[0];
    const float* w = (const float*)d_in[1];
    if (in_sizes[0] == 49152) { const float* t = x; x = w; w = t; }
    float* out = (float*)d_out;

    gather_xs<<<(128 * NTOK) / 256, 256>>>(x);

    dim3 g1(NTOK / 128, 384 / 64);
    qkv_proj<<<g1, 256>>>(w);

    dim3 gq(NTOK / 128, HEADS);
    conv_qk<<<gq, 128>>>();

    dim3 g3(NTOK / 128, HEADS, NCHUNK);
    attn_mma<<<g3, 128>>>();

    reduce_out<<<(HEADS * NTOK * 32) / 256, 256>>>(out);
}

// round 14
// speedup vs baseline: 1.1907x; 1.1907x over previous
#include <cuda_runtime.h>
#include <cuda_bf16.h>
#include <cuda_fp16.h>

// ---------------------------------------------------------------------------
// DiffAttention — R13: R8 base (m16/warp, NCHUNK=4, cp.async, 5 blk/SM) with
// fp16 datapath: Q hi/lo fp16 + K single fp16 (QK = 2 MMAs, was 3) and
// fp16 P/V. Cuts tensor work 20% and ldsm/L1 traffic 33%.
// ---------------------------------------------------------------------------

#define NTOK   4096
#define HEADS  4
#define NCHUNK 4
#define MPER   (NTOK / NCHUNK)     // 1024 keys per chunk
#define NIT    (MPER / 64)         // 16 key-tiles
#define STAGE  9728                // K 5120 + V 4608
#define LAMBDA 0.1f

// Scratch (static device globals; no allocation allowed)
__device__ float  g_xs [128 * NTOK];
__device__ float  g_qkv[384 * NTOK];
__device__ __half g_qh[HEADS * NTOK * 32];   // [h][n][d] fp16 hi (scale*log2e folded)
__device__ __half g_ql[HEADS * NTOK * 32];   // [h][n][d] fp16 lo
__device__ __half g_kf[HEADS * NTOK * 32];   // [h][n][d] fp16
__device__ __half g_vb[HEADS * 32 * NTOK];   // [h][d][n] fp16
__device__ float  g_po[NCHUNK * HEADS * NTOK * 64];  // [ch][h][n][2][32]
__device__ float  g_pl[NCHUNK * HEADS * NTOK * 2];   // [ch][h][n][2]

// ---- PTX helpers ----------------------------------------------------------
__device__ __forceinline__ float ex2(float a) {
    float r; asm("ex2.approx.ftz.f32 %0, %1;" : "=f"(r) : "f"(a)); return r;
}
__device__ __forceinline__ unsigned cvt2h(float hi, float lo) {  // {lo,hi} f16x2
    unsigned d; asm("cvt.rn.f16x2.f32 %0,%1,%2;" : "=r"(d) : "f"(hi), "f"(lo)); return d;
}
__device__ __forceinline__ void ldsm4(unsigned* r, unsigned a) {
    asm volatile("ldmatrix.sync.aligned.m8n8.x4.shared.b16 {%0,%1,%2,%3},[%4];"
                 : "=r"(r[0]), "=r"(r[1]), "=r"(r[2]), "=r"(r[3]) : "r"(a));
}
__device__ __forceinline__ void mma16816h(float* c, const unsigned* a,
                                          unsigned b0, unsigned b1) {
    asm("mma.sync.aligned.m16n8k16.row.col.f32.f16.f16.f32 "
        "{%0,%1,%2,%3},{%4,%5,%6,%7},{%8,%9},{%0,%1,%2,%3};"
        : "+f"(c[0]), "+f"(c[1]), "+f"(c[2]), "+f"(c[3])
        : "r"(a[0]), "r"(a[1]), "r"(a[2]), "r"(a[3]), "r"(b0), "r"(b1));
}
__device__ __forceinline__ void cpa16(unsigned dst, const void* src) {
    asm volatile("cp.async.ca.shared.global [%0], [%1], 16;" :: "r"(dst), "l"(src));
}
__device__ __forceinline__ void cpa_commit() {
    asm volatile("cp.async.commit_group;");
}
template <int N> __device__ __forceinline__ void cpa_wait() {
    asm volatile("cp.async.wait_group %0;" :: "n"(N));
}

// ---------------------------------------------------------------------------
// Kernel 0: compact ::2 subsample -> g_xs[c][n]
// ---------------------------------------------------------------------------
__global__ __launch_bounds__(256) void gather_xs(const float* __restrict__ x)
{
    const int idx = blockIdx.x * 256 + threadIdx.x;
    const int n = idx & 4095, c = idx >> 12;
    const int hh = n >> 8, ww = (n >> 4) & 15, zz = n & 15;
    g_xs[idx] = x[c * 32768 + hh * 2048 + ww * 64 + zz * 2];
}

// ---------------------------------------------------------------------------
// Kernel 1: QKV projection GEMM with fused V->fp16 epilogue
// ---------------------------------------------------------------------------
__global__ __launch_bounds__(256) void qkv_proj(const float* __restrict__ w)
{
    __shared__ __align__(16) float ws[16][64];
    __shared__ __align__(16) float xs[16][128];

    const int tid = threadIdx.x;
    const int tx = tid & 15, ty = tid >> 4;
    const int n0 = blockIdx.x * 128, o0 = blockIdx.y * 64;

    float acc[4][8];
#pragma unroll
    for (int i = 0; i < 4; i++)
#pragma unroll
        for (int j = 0; j < 8; j++) acc[i][j] = 0.f;

    for (int c0 = 0; c0 < 128; c0 += 16) {
        __syncthreads();
        {
            const int o = tid >> 2, cc = (tid & 3) * 4;
            float4 wv = *(const float4*)&w[(o0 + o) * 128 + c0 + cc];
            ws[cc + 0][o] = wv.x; ws[cc + 1][o] = wv.y;
            ws[cc + 2][o] = wv.z; ws[cc + 3][o] = wv.w;
        }
#pragma unroll
        for (int r = 0; r < 2; r++) {
            const int i = tid * 2 + r, cc = i >> 5, f = i & 31;
            ((float4*)&xs[cc][0])[f] = *(const float4*)&g_xs[(c0 + cc) * NTOK + n0 + f * 4];
        }
        __syncthreads();
#pragma unroll
        for (int cc = 0; cc < 16; cc++) {
            const float4 wv = *(const float4*)&ws[cc][ty * 4];
            const float4 xa = *(const float4*)&xs[cc][tx * 8];
            const float4 xb = *(const float4*)&xs[cc][tx * 8 + 4];
            const float wr[4] = {wv.x, wv.y, wv.z, wv.w};
#pragma unroll
            for (int i = 0; i < 4; i++) {
                acc[i][0] += wr[i] * xa.x; acc[i][1] += wr[i] * xa.y;
                acc[i][2] += wr[i] * xa.z; acc[i][3] += wr[i] * xa.w;
                acc[i][4] += wr[i] * xb.x; acc[i][5] += wr[i] * xb.y;
                acc[i][6] += wr[i] * xb.z; acc[i][7] += wr[i] * xb.w;
            }
        }
    }
#pragma unroll
    for (int i = 0; i < 4; i++) {
        const int o = o0 + ty * 4 + i;
        float* dst = &g_qkv[o * NTOK + n0 + tx * 8];
        *(float4*)(dst)     = make_float4(acc[i][0], acc[i][1], acc[i][2], acc[i][3]);
        *(float4*)(dst + 4) = make_float4(acc[i][4], acc[i][5], acc[i][6], acc[i][7]);
        const int om = o % 96;
        if (om >= 64) {
            const int hd = (o / 96) * 32 + om - 64;
            uint4 vo;
            vo.x = cvt2h(acc[i][1], acc[i][0]); vo.y = cvt2h(acc[i][3], acc[i][2]);
            vo.z = cvt2h(acc[i][5], acc[i][4]); vo.w = cvt2h(acc[i][7], acc[i][6]);
            *(uint4*)(g_vb + (size_t)hd * NTOK + n0 + tx * 8) = vo;
        }
    }
}

// ---------------------------------------------------------------------------
// Kernel 2: Q -> fp16 hi/lo, K -> fp16 single; [h][n][d] via smem transpose
// ---------------------------------------------------------------------------
__global__ __launch_bounds__(128) void conv_qk()
{
    __shared__ float s[128][33];
    const int tid = threadIdx.x;
    const int h = blockIdx.y;
    const int n0 = blockIdx.x * 128;
    const int n = n0 + tid;
    const float SCLL = 0.17677669529663687f * 1.4426950408889634f;

#pragma unroll
    for (int pass = 0; pass < 2; pass++) {
        const float* src = g_qkv + (h * 96 + pass * 32) * NTOK;
        const float scl = pass ? 1.f : SCLL;
        __half* dh = (pass ? g_kf : g_qh) + ((size_t)h * NTOK + n) * 32;
        __half* dl = g_ql + ((size_t)h * NTOK + n) * 32;

        __syncthreads();
#pragma unroll
        for (int d = 0; d < 32; d++) s[tid][d] = src[d * NTOK + n0 + tid];
        __syncthreads();

#pragma unroll
        for (int d0 = 0; d0 < 32; d0 += 8) {
            __half a[8], b[8];
#pragma unroll
            for (int dd = 0; dd < 8; dd++) {
                float v = s[tid][d0 + dd] * scl;
                __half x1 = __float2half_rn(v);
                a[dd] = x1;
                b[dd] = __float2half_rn(v - __half2float(x1));
            }
            *(uint4*)(dh + d0) = *(uint4*)a;
            if (pass == 0) *(uint4*)(dl + d0) = *(uint4*)b;
        }
    }
}

// ---------------------------------------------------------------------------
// Kernel 3: warp-MMA flash attention (fp16, 2-MMA QK), cp.async pipeline.
// grid (64 q-tiles, 4 heads, 4 chunks) = 1024 blocks, block 128.
// ---------------------------------------------------------------------------
__global__ __launch_bounds__(128, 5) void attn_mma()
{
    __shared__ __align__(16) unsigned char sm[2 * STAGE];
    const int tid = threadIdx.x;
    const int lane = tid & 31, wp = tid >> 5;
    const int h = blockIdx.y;
    const int q0 = blockIdx.x * 64;
    const int ch = blockIdx.z;

    const unsigned sbase = (unsigned)__cvta_generic_to_shared(sm);

    // ---- stage Q hi/lo (64 rows x 64B, padded 80B), build A-frags, release
    {
        const char* qhp = (const char*)(g_qh + ((size_t)h * NTOK + q0) * 32);
        const char* qlp = (const char*)(g_ql + ((size_t)h * NTOK + q0) * 32);
#pragma unroll
        for (int r = 0; r < 2; r++) {
            int i = tid * 2 + r, row = i >> 2, c = i & 3;
            *(uint4*)(sm + row * 80 + c * 16)        = *(const uint4*)(qhp + row * 64 + c * 16);
            *(uint4*)(sm + 5120 + row * 80 + c * 16) = *(const uint4*)(qlp + row * 64 + c * 16);
        }
    }
    __syncthreads();
    unsigned Qh1[4], Qh2[4], Ql1[4], Ql2[4];
    {
        const unsigned ar = sbase + (wp * 16 + (lane & 15)) * 80 + (lane >> 4) * 16;
        ldsm4(Qh1, ar);
        ldsm4(Qh2, ar + 32);
        ldsm4(Ql1, ar + 5120);
        ldsm4(Ql2, ar + 5120 + 32);
    }
    __syncthreads();   // Q consumed; smem free for pipeline

    float O1[4][4], O2[4][4];
#pragma unroll
    for (int i = 0; i < 4; i++)
#pragma unroll
        for (int j = 0; j < 4; j++) { O1[i][j] = 0.f; O2[i][j] = 0.f; }
    float l1a = 0.f, l1b = 0.f, l2a = 0.f, l2b = 0.f;

    const char* kfp = (const char*)(g_kf + ((size_t)h * NTOK + ch * MPER) * 32);
    const char* vbp = (const char*)(g_vb + (size_t)h * 32 * NTOK + ch * MPER);

    // cp.async geometry: per thread 2 K + 2 V chunks (16B each)
    const int i0 = tid * 2, i1 = tid * 2 + 1;
    const int kr0 = i0 >> 2, kc0 = i0 & 3;
    const int kr1 = i1 >> 2, kc1 = i1 & 3;
    const int vr0 = i0 >> 3, vc0 = i0 & 7;
    const int vr1 = i1 >> 3, vc1 = i1 & 7;

    const char* skf0 = kfp + kr0 * 64 + kc0 * 16;   // advance 4096 per tile
    const char* skf1 = kfp + kr1 * 64 + kc1 * 16;
    const char* svv0 = vbp + vr0 * 8192 + vc0 * 16; // advance 128 per tile
    const char* svv1 = vbp + vr1 * 8192 + vc1 * 16;

    const unsigned dkf0 = kr0 * 80 + kc0 * 16;
    const unsigned dkf1 = kr1 * 80 + kc1 * 16;
    const unsigned dvv0 = 5120 + vr0 * 144 + vc0 * 16;
    const unsigned dvv1 = 5120 + vr1 * 144 + vc1 * 16;

    // B-fragment ldmatrix geometry
    const int bg = lane >> 3;
    const unsigned brow80  = (unsigned)(((bg >> 1) * 8 + (lane & 7)) * 80);
    const unsigned vrow144 = (unsigned)(((bg >> 1) * 8 + (lane & 7)) * 144);
    const unsigned bk16    = (unsigned)((bg & 1) * 16);

#define PREFETCH(stage, tile)                                            \
    do {                                                                 \
        const unsigned db = sbase + (stage) * STAGE;                     \
        const int ko = (tile) * (64 * 64);                               \
        const int vo = (tile) * 128;                                     \
        cpa16(db + dkf0, skf0 + ko);                                     \
        cpa16(db + dkf1, skf1 + ko);                                     \
        cpa16(db + dvv0, svv0 + vo);                                     \
        cpa16(db + dvv1, svv1 + vo);                                     \
        cpa_commit();                                                    \
    } while (0)

    PREFETCH(0, 0);

#pragma unroll 1
    for (int it = 0; it < NIT; it++) {
        if (it + 1 < NIT) {
            PREFETCH((it + 1) & 1, it + 1);
            cpa_wait<1>();
        } else {
            cpa_wait<0>();
        }
        __syncthreads();

        const unsigned sb = sbase + (it & 1) * STAGE;
        const unsigned sKF = sb, sVV = sb + 5120;

#pragma unroll
        for (int np = 0; np < 4; np++) {
            const unsigned kra = (unsigned)(np * (16 * 80)) + brow80;
            unsigned kb1[4], kb2[4];
            ldsm4(kb1, sKF + kra + bk16);        // K d0-15
            ldsm4(kb2, sKF + kra + 32 + bk16);   // K d16-31

            float s1[8] = {0, 0, 0, 0, 0, 0, 0, 0};
            float s2[8] = {0, 0, 0, 0, 0, 0, 0, 0};
            // S1 = (Qh1 + Ql1) * K1   (2 MMAs per n8-tile)
            mma16816h(s1,     Qh1, kb1[0], kb1[1]);
            mma16816h(s1,     Ql1, kb1[0], kb1[1]);
            mma16816h(s1 + 4, Qh1, kb1[2], kb1[3]);
            mma16816h(s1 + 4, Ql1, kb1[2], kb1[3]);
            // S2 = (Qh2 + Ql2) * K2
            mma16816h(s2,     Qh2, kb2[0], kb2[1]);
            mma16816h(s2,     Ql2, kb2[0], kb2[1]);
            mma16816h(s2 + 4, Qh2, kb2[2], kb2[3]);
            mma16816h(s2 + 4, Ql2, kb2[2], kb2[3]);

            float p1[8], p2[8];
#pragma unroll
            for (int e = 0; e < 8; e++) { p1[e] = ex2(s1[e]); p2[e] = ex2(s2[e]); }
            l1a += p1[0] + p1[1] + p1[4] + p1[5];
            l1b += p1[2] + p1[3] + p1[6] + p1[7];
            l2a += p2[0] + p2[1] + p2[4] + p2[5];
            l2b += p2[2] + p2[3] + p2[6] + p2[7];

            unsigned P1[4] = { cvt2h(p1[1], p1[0]), cvt2h(p1[3], p1[2]),
                               cvt2h(p1[5], p1[4]), cvt2h(p1[7], p1[6]) };
            unsigned P2[4] = { cvt2h(p2[1], p2[0]), cvt2h(p2[3], p2[2]),
                               cvt2h(p2[5], p2[4]), cvt2h(p2[7], p2[6]) };

            unsigned va[4], vb2[4];
            const unsigned vca = (unsigned)(np * 32) + bk16;
            ldsm4(va,  sVV + vrow144 + vca);
            ldsm4(vb2, sVV + 16 * 144 + vrow144 + vca);

            mma16816h(O1[0], P1, va[0],  va[1]);
            mma16816h(O1[1], P1, va[2],  va[3]);
            mma16816h(O1[2], P1, vb2[0], vb2[1]);
            mma16816h(O1[3], P1, vb2[2], vb2[3]);
            mma16816h(O2[0], P2, va[0],  va[1]);
            mma16816h(O2[1], P2, va[2],  va[3]);
            mma16816h(O2[2], P2, vb2[0], vb2[1]);
            mma16816h(O2[3], P2, vb2[2], vb2[3]);
        }
        __syncthreads();   // all warps done with this stage before overwrite
    }

    l1a += __shfl_xor_sync(0xffffffffu, l1a, 1); l1a += __shfl_xor_sync(0xffffffffu, l1a, 2);
    l1b += __shfl_xor_sync(0xffffffffu, l1b, 1); l1b += __shfl_xor_sync(0xffffffffu, l1b, 2);
    l2a += __shfl_xor_sync(0xffffffffu, l2a, 1); l2a += __shfl_xor_sync(0xffffffffu, l2a, 2);
    l2b += __shfl_xor_sync(0xffffffffu, l2b, 1); l2b += __shfl_xor_sync(0xffffffffu, l2b, 2);

    // write chunk partials (unnormalized O, row-sums l)
    const int row = q0 + wp * 16 + (lane >> 2);
    const int colb = (lane & 3) * 2;
    float* po  = g_po + ((size_t)((ch * HEADS + h) * NTOK) + row) * 64;
    float* po8 = po + 8 * 64;
#pragma unroll
    for (int t = 0; t < 4; t++) {
        const int col = t * 8 + colb;
        *(float2*)(po  + col)      = make_float2(O1[t][0], O1[t][1]);
        *(float2*)(po  + 32 + col) = make_float2(O2[t][0], O2[t][1]);
        *(float2*)(po8 + col)      = make_float2(O1[t][2], O1[t][3]);
        *(float2*)(po8 + 32 + col) = make_float2(O2[t][2], O2[t][3]);
    }
    if ((lane & 3) == 0) {
        float* pl = g_pl + ((size_t)((ch * HEADS + h) * NTOK) + row) * 2;
        pl[0] = l1a; pl[1] = l2a;
        pl[16] = l1b; pl[17] = l2b;     // row+8
    }
}

// ---------------------------------------------------------------------------
// Kernel 4: combine chunk partials -> out[h*131072 + n*32 + d]
// ---------------------------------------------------------------------------
__global__ __launch_bounds__(256) void reduce_out(float* __restrict__ out)
{
    const int idx = blockIdx.x * 256 + threadIdx.x;
    const int d  = idx & 31;
    const int hn = idx >> 5;

    float s1 = 0.f, s2 = 0.f, L1 = 0.f, L2 = 0.f;
#pragma unroll
    for (int ch = 0; ch < NCHUNK; ch++) {
        const float* po = g_po + (size_t)(ch * HEADS * NTOK + hn) * 64;
        s1 += po[d];
        s2 += po[32 + d];
        const float* pl = g_pl + (size_t)(ch * HEADS * NTOK + hn) * 2;
        L1 += pl[0];
        L2 += pl[1];
    }
    out[idx] = s1 / L1 - LAMBDA * s2 / L2;
}

// ---------------------------------------------------------------------------
extern "C" void kernel_launch(void* const* d_in, const int* in_sizes, int n_in,
                              void* d_out, int out_size)
{
    const float* x = (const float*)d_in[0];
    const float* w = (const float*)d_in[1];
    if (in_sizes[0] == 49152) { const float* t = x; x = w; w = t; }
    float* out = (float*)d_out;

    gather_xs<<<(128 * NTOK) / 256, 256>>>(x);

    dim3 g1(NTOK / 128, 384 / 64);
    qkv_proj<<<g1, 256>>>(w);

    dim3 gq(NTOK / 128, HEADS);
    conv_qk<<<gq, 128>>>();

    dim3 g3(NTOK / 64, HEADS, NCHUNK);
    attn_mma<<<g3, 128>>>();

    reduce_out<<<(HEADS * NTOK * 32) / 256, 256>>>(out);
}

// round 16
// speedup vs baseline: 1.3352x; 1.1214x over previous
#include <cuda_runtime.h>
#include <cuda_bf16.h>
#include <cuda_fp16.h>

// ---------------------------------------------------------------------------
// DiffAttention — R15: single-fp16 Q (Ql dropped; error budget 9x allowed it).
// QK = 1 MMA per n8-tile per half -> 12 MMAs/np (was 16). Base: R13.
// ---------------------------------------------------------------------------

#define NTOK   4096
#define HEADS  4
#define NCHUNK 4
#define MPER   (NTOK / NCHUNK)     // 1024 keys per chunk
#define NIT    (MPER / 64)         // 16 key-tiles
#define STAGE  9728                // K 5120 + V 4608
#define LAMBDA 0.1f

// Scratch (static device globals; no allocation allowed)
__device__ float  g_xs [128 * NTOK];
__device__ float  g_qkv[384 * NTOK];
__device__ __half g_qh[HEADS * NTOK * 32];   // [h][n][d] fp16 (scale*log2e folded)
__device__ __half g_kf[HEADS * NTOK * 32];   // [h][n][d] fp16
__device__ __half g_vb[HEADS * 32 * NTOK];   // [h][d][n] fp16
__device__ float  g_po[NCHUNK * HEADS * NTOK * 64];  // [ch][h][n][2][32]
__device__ float  g_pl[NCHUNK * HEADS * NTOK * 2];   // [ch][h][n][2]

// ---- PTX helpers ----------------------------------------------------------
__device__ __forceinline__ float ex2(float a) {
    float r; asm("ex2.approx.ftz.f32 %0, %1;" : "=f"(r) : "f"(a)); return r;
}
__device__ __forceinline__ unsigned cvt2h(float hi, float lo) {  // {lo,hi} f16x2
    unsigned d; asm("cvt.rn.f16x2.f32 %0,%1,%2;" : "=r"(d) : "f"(hi), "f"(lo)); return d;
}
__device__ __forceinline__ void ldsm4(unsigned* r, unsigned a) {
    asm volatile("ldmatrix.sync.aligned.m8n8.x4.shared.b16 {%0,%1,%2,%3},[%4];"
                 : "=r"(r[0]), "=r"(r[1]), "=r"(r[2]), "=r"(r[3]) : "r"(a));
}
__device__ __forceinline__ void mma16816h(float* c, const unsigned* a,
                                          unsigned b0, unsigned b1) {
    asm("mma.sync.aligned.m16n8k16.row.col.f32.f16.f16.f32 "
        "{%0,%1,%2,%3},{%4,%5,%6,%7},{%8,%9},{%0,%1,%2,%3};"
        : "+f"(c[0]), "+f"(c[1]), "+f"(c[2]), "+f"(c[3])
        : "r"(a[0]), "r"(a[1]), "r"(a[2]), "r"(a[3]), "r"(b0), "r"(b1));
}
__device__ __forceinline__ void cpa16(unsigned dst, const void* src) {
    asm volatile("cp.async.ca.shared.global [%0], [%1], 16;" :: "r"(dst), "l"(src));
}
__device__ __forceinline__ void cpa_commit() {
    asm volatile("cp.async.commit_group;");
}
template <int N> __device__ __forceinline__ void cpa_wait() {
    asm volatile("cp.async.wait_group %0;" :: "n"(N));
}

// ---------------------------------------------------------------------------
// Kernel 0: compact ::2 subsample -> g_xs[c][n]
// ---------------------------------------------------------------------------
__global__ __launch_bounds__(256) void gather_xs(const float* __restrict__ x)
{
    const int idx = blockIdx.x * 256 + threadIdx.x;
    const int n = idx & 4095, c = idx >> 12;
    const int hh = n >> 8, ww = (n >> 4) & 15, zz = n & 15;
    g_xs[idx] = x[c * 32768 + hh * 2048 + ww * 64 + zz * 2];
}

// ---------------------------------------------------------------------------
// Kernel 1: QKV projection GEMM with fused V->fp16 epilogue
// ---------------------------------------------------------------------------
__global__ __launch_bounds__(256) void qkv_proj(const float* __restrict__ w)
{
    __shared__ __align__(16) float ws[16][64];
    __shared__ __align__(16) float xs[16][128];

    const int tid = threadIdx.x;
    const int tx = tid & 15, ty = tid >> 4;
    const int n0 = blockIdx.x * 128, o0 = blockIdx.y * 64;

    float acc[4][8];
#pragma unroll
    for (int i = 0; i < 4; i++)
#pragma unroll
        for (int j = 0; j < 8; j++) acc[i][j] = 0.f;

    for (int c0 = 0; c0 < 128; c0 += 16) {
        __syncthreads();
        {
            const int o = tid >> 2, cc = (tid & 3) * 4;
            float4 wv = *(const float4*)&w[(o0 + o) * 128 + c0 + cc];
            ws[cc + 0][o] = wv.x; ws[cc + 1][o] = wv.y;
            ws[cc + 2][o] = wv.z; ws[cc + 3][o] = wv.w;
        }
#pragma unroll
        for (int r = 0; r < 2; r++) {
            const int i = tid * 2 + r, cc = i >> 5, f = i & 31;
            ((float4*)&xs[cc][0])[f] = *(const float4*)&g_xs[(c0 + cc) * NTOK + n0 + f * 4];
        }
        __syncthreads();
#pragma unroll
        for (int cc = 0; cc < 16; cc++) {
            const float4 wv = *(const float4*)&ws[cc][ty * 4];
            const float4 xa = *(const float4*)&xs[cc][tx * 8];
            const float4 xb = *(const float4*)&xs[cc][tx * 8 + 4];
            const float wr[4] = {wv.x, wv.y, wv.z, wv.w};
#pragma unroll
            for (int i = 0; i < 4; i++) {
                acc[i][0] += wr[i] * xa.x; acc[i][1] += wr[i] * xa.y;
                acc[i][2] += wr[i] * xa.z; acc[i][3] += wr[i] * xa.w;
                acc[i][4] += wr[i] * xb.x; acc[i][5] += wr[i] * xb.y;
                acc[i][6] += wr[i] * xb.z; acc[i][7] += wr[i] * xb.w;
            }
        }
    }
#pragma unroll
    for (int i = 0; i < 4; i++) {
        const int o = o0 + ty * 4 + i;
        float* dst = &g_qkv[o * NTOK + n0 + tx * 8];
        *(float4*)(dst)     = make_float4(acc[i][0], acc[i][1], acc[i][2], acc[i][3]);
        *(float4*)(dst + 4) = make_float4(acc[i][4], acc[i][5], acc[i][6], acc[i][7]);
        const int om = o % 96;
        if (om >= 64) {
            const int hd = (o / 96) * 32 + om - 64;
            uint4 vo;
            vo.x = cvt2h(acc[i][1], acc[i][0]); vo.y = cvt2h(acc[i][3], acc[i][2]);
            vo.z = cvt2h(acc[i][5], acc[i][4]); vo.w = cvt2h(acc[i][7], acc[i][6]);
            *(uint4*)(g_vb + (size_t)hd * NTOK + n0 + tx * 8) = vo;
        }
    }
}

// ---------------------------------------------------------------------------
// Kernel 2: Q/K -> single fp16 [h][n][d] via smem transpose
// ---------------------------------------------------------------------------
__global__ __launch_bounds__(128) void conv_qk()
{
    __shared__ float s[128][33];
    const int tid = threadIdx.x;
    const int h = blockIdx.y;
    const int n0 = blockIdx.x * 128;
    const int n = n0 + tid;
    const float SCLL = 0.17677669529663687f * 1.4426950408889634f;

#pragma unroll
    for (int pass = 0; pass < 2; pass++) {
        const float* src = g_qkv + (h * 96 + pass * 32) * NTOK;
        const float scl = pass ? 1.f : SCLL;
        __half* dh = (pass ? g_kf : g_qh) + ((size_t)h * NTOK + n) * 32;

        __syncthreads();
#pragma unroll
        for (int d = 0; d < 32; d++) s[tid][d] = src[d * NTOK + n0 + tid];
        __syncthreads();

#pragma unroll
        for (int d0 = 0; d0 < 32; d0 += 8) {
            __half a[8];
#pragma unroll
            for (int dd = 0; dd < 8; dd++)
                a[dd] = __float2half_rn(s[tid][d0 + dd] * scl);
            *(uint4*)(dh + d0) = *(uint4*)a;
        }
    }
}

// ---------------------------------------------------------------------------
// Kernel 3: warp-MMA flash attention (fp16, 1-MMA QK per n8/half).
// grid (64 q-tiles, 4 heads, 4 chunks) = 1024 blocks, block 128.
// ---------------------------------------------------------------------------
__global__ __launch_bounds__(128, 5) void attn_mma()
{
    __shared__ __align__(16) unsigned char sm[2 * STAGE];
    const int tid = threadIdx.x;
    const int lane = tid & 31, wp = tid >> 5;
    const int h = blockIdx.y;
    const int q0 = blockIdx.x * 64;
    const int ch = blockIdx.z;

    const unsigned sbase = (unsigned)__cvta_generic_to_shared(sm);

    // ---- stage Q (64 rows x 64B, padded 80B), build A-frags, release
    {
        const char* qhp = (const char*)(g_qh + ((size_t)h * NTOK + q0) * 32);
#pragma unroll
        for (int r = 0; r < 2; r++) {
            int i = tid * 2 + r, row = i >> 2, c = i & 3;
            *(uint4*)(sm + row * 80 + c * 16) = *(const uint4*)(qhp + row * 64 + c * 16);
        }
    }
    __syncthreads();
    unsigned Qh1[4], Qh2[4];
    {
        const unsigned ar = sbase + (wp * 16 + (lane & 15)) * 80 + (lane >> 4) * 16;
        ldsm4(Qh1, ar);
        ldsm4(Qh2, ar + 32);
    }
    __syncthreads();   // Q consumed; smem free for pipeline

    float O1[4][4], O2[4][4];
#pragma unroll
    for (int i = 0; i < 4; i++)
#pragma unroll
        for (int j = 0; j < 4; j++) { O1[i][j] = 0.f; O2[i][j] = 0.f; }
    float l1a = 0.f, l1b = 0.f, l2a = 0.f, l2b = 0.f;

    const char* kfp = (const char*)(g_kf + ((size_t)h * NTOK + ch * MPER) * 32);
    const char* vbp = (const char*)(g_vb + (size_t)h * 32 * NTOK + ch * MPER);

    // cp.async geometry: per thread 2 K + 2 V chunks (16B each)
    const int i0 = tid * 2, i1 = tid * 2 + 1;
    const int kr0 = i0 >> 2, kc0 = i0 & 3;
    const int kr1 = i1 >> 2, kc1 = i1 & 3;
    const int vr0 = i0 >> 3, vc0 = i0 & 7;
    const int vr1 = i1 >> 3, vc1 = i1 & 7;

    const char* skf0 = kfp + kr0 * 64 + kc0 * 16;   // advance 4096 per tile
    const char* skf1 = kfp + kr1 * 64 + kc1 * 16;
    const char* svv0 = vbp + vr0 * 8192 + vc0 * 16; // advance 128 per tile
    const char* svv1 = vbp + vr1 * 8192 + vc1 * 16;

    const unsigned dkf0 = kr0 * 80 + kc0 * 16;
    const unsigned dkf1 = kr1 * 80 + kc1 * 16;
    const unsigned dvv0 = 5120 + vr0 * 144 + vc0 * 16;
    const unsigned dvv1 = 5120 + vr1 * 144 + vc1 * 16;

    // B-fragment ldmatrix geometry
    const int bg = lane >> 3;
    const unsigned brow80  = (unsigned)(((bg >> 1) * 8 + (lane & 7)) * 80);
    const unsigned vrow144 = (unsigned)(((bg >> 1) * 8 + (lane & 7)) * 144);
    const unsigned bk16    = (unsigned)((bg & 1) * 16);

#define PREFETCH(stage, tile)                                            \
    do {                                                                 \
        const unsigned db = sbase + (stage) * STAGE;                     \
        const int ko = (tile) * (64 * 64);                               \
        const int vo = (tile) * 128;                                     \
        cpa16(db + dkf0, skf0 + ko);                                     \
        cpa16(db + dkf1, skf1 + ko);                                     \
        cpa16(db + dvv0, svv0 + vo);                                     \
        cpa16(db + dvv1, svv1 + vo);                                     \
        cpa_commit();                                                    \
    } while (0)

    PREFETCH(0, 0);

#pragma unroll 1
    for (int it = 0; it < NIT; it++) {
        if (it + 1 < NIT) {
            PREFETCH((it + 1) & 1, it + 1);
            cpa_wait<1>();
        } else {
            cpa_wait<0>();
        }
        __syncthreads();

        const unsigned sb = sbase + (it & 1) * STAGE;
        const unsigned sKF = sb, sVV = sb + 5120;

#pragma unroll
        for (int np = 0; np < 4; np++) {
            const unsigned kra = (unsigned)(np * (16 * 80)) + brow80;
            unsigned kb1[4], kb2[4];
            ldsm4(kb1, sKF + kra + bk16);        // K d0-15
            ldsm4(kb2, sKF + kra + 32 + bk16);   // K d16-31

            float s1[8] = {0, 0, 0, 0, 0, 0, 0, 0};
            float s2[8] = {0, 0, 0, 0, 0, 0, 0, 0};
            mma16816h(s1,     Qh1, kb1[0], kb1[1]);
            mma16816h(s1 + 4, Qh1, kb1[2], kb1[3]);
            mma16816h(s2,     Qh2, kb2[0], kb2[1]);
            mma16816h(s2 + 4, Qh2, kb2[2], kb2[3]);

            float p1[8], p2[8];
#pragma unroll
            for (int e = 0; e < 8; e++) { p1[e] = ex2(s1[e]); p2[e] = ex2(s2[e]); }
            l1a += p1[0] + p1[1] + p1[4] + p1[5];
            l1b += p1[2] + p1[3] + p1[6] + p1[7];
            l2a += p2[0] + p2[1] + p2[4] + p2[5];
            l2b += p2[2] + p2[3] + p2[6] + p2[7];

            unsigned P1[4] = { cvt2h(p1[1], p1[0]), cvt2h(p1[3], p1[2]),
                               cvt2h(p1[5], p1[4]), cvt2h(p1[7], p1[6]) };
            unsigned P2[4] = { cvt2h(p2[1], p2[0]), cvt2h(p2[3], p2[2]),
                               cvt2h(p2[5], p2[4]), cvt2h(p2[7], p2[6]) };

            unsigned va[4], vb2[4];
            const unsigned vca = (unsigned)(np * 32) + bk16;
            ldsm4(va,  sVV + vrow144 + vca);
            ldsm4(vb2, sVV + 16 * 144 + vrow144 + vca);

            mma16816h(O1[0], P1, va[0],  va[1]);
            mma16816h(O1[1], P1, va[2],  va[3]);
            mma16816h(O1[2], P1, vb2[0], vb2[1]);
            mma16816h(O1[3], P1, vb2[2], vb2[3]);
            mma16816h(O2[0], P2, va[0],  va[1]);
            mma16816h(O2[1], P2, va[2],  va[3]);
            mma16816h(O2[2], P2, vb2[0], vb2[1]);
            mma16816h(O2[3], P2, vb2[2], vb2[3]);
        }
        __syncthreads();   // all warps done with this stage before overwrite
    }

    l1a += __shfl_xor_sync(0xffffffffu, l1a, 1); l1a += __shfl_xor_sync(0xffffffffu, l1a, 2);
    l1b += __shfl_xor_sync(0xffffffffu, l1b, 1); l1b += __shfl_xor_sync(0xffffffffu, l1b, 2);
    l2a += __shfl_xor_sync(0xffffffffu, l2a, 1); l2a += __shfl_xor_sync(0xffffffffu, l2a, 2);
    l2b += __shfl_xor_sync(0xffffffffu, l2b, 1); l2b += __shfl_xor_sync(0xffffffffu, l2b, 2);

    // write chunk partials (unnormalized O, row-sums l)
    const int row = q0 + wp * 16 + (lane >> 2);
    const int colb = (lane & 3) * 2;
    float* po  = g_po + ((size_t)((ch * HEADS + h) * NTOK) + row) * 64;
    float* po8 = po + 8 * 64;
#pragma unroll
    for (int t = 0; t < 4; t++) {
        const int col = t * 8 + colb;
        *(float2*)(po  + col)      = make_float2(O1[t][0], O1[t][1]);
        *(float2*)(po  + 32 + col) = make_float2(O2[t][0], O2[t][1]);
        *(float2*)(po8 + col)      = make_float2(O1[t][2], O1[t][3]);
        *(float2*)(po8 + 32 + col) = make_float2(O2[t][2], O2[t][3]);
    }
    if ((lane & 3) == 0) {
        float* pl = g_pl + ((size_t)((ch * HEADS + h) * NTOK) + row) * 2;
        pl[0] = l1a; pl[1] = l2a;
        pl[16] = l1b; pl[17] = l2b;     // row+8
    }
}

// ---------------------------------------------------------------------------
// Kernel 4: combine chunk partials -> out[h*131072 + n*32 + d]
// ---------------------------------------------------------------------------
__global__ __launch_bounds__(256) void reduce_out(float* __restrict__ out)
{
    const int idx = blockIdx.x * 256 + threadIdx.x;
    const int d  = idx & 31;
    const int hn = idx >> 5;

    float s1 = 0.f, s2 = 0.f, L1 = 0.f, L2 = 0.f;
#pragma unroll
    for (int ch = 0; ch < NCHUNK; ch++) {
        const float* po = g_po + (size_t)(ch * HEADS * NTOK + hn) * 64;
        s1 += po[d];
        s2 += po[32 + d];
        const float* pl = g_pl + (size_t)(ch * HEADS * NTOK + hn) * 2;
        L1 += pl[0];
        L2 += pl[1];
    }
    out[idx] = s1 / L1 - LAMBDA * s2 / L2;
}

// ---------------------------------------------------------------------------
extern "C" void kernel_launch(void* const* d_in, const int* in_sizes, int n_in,
                              void* d_out, int out_size)
{
    const float* x = (const float*)d_in[0];
    const float* w = (const float*)d_in[1];
    if (in_sizes[0] == 49152) { const float* t = x; x = w; w = t; }
    float* out = (float*)d_out;

    gather_xs<<<(128 * NTOK) / 256, 256>>>(x);

    dim3 g1(NTOK / 128, 384 / 64);
    qkv_proj<<<g1, 256>>>(w);

    dim3 gq(NTOK / 128, HEADS);
    conv_qk<<<gq, 128>>>();

    dim3 g3(NTOK / 64, HEADS, NCHUNK);
    attn_mma<<<g3, 128>>>();

    reduce_out<<<(HEADS * NTOK * 32) / 256, 256>>>(out);
}